// round 1
// baseline (speedup 1.0000x reference)
#include <cuda_runtime.h>
#include <cuda_bf16.h>

#define BB 4096
#define TT 16
#define HH 768
#define AA 128
#define VV 16
#define LL 2
#define MTILE 32
#define KC 64      // k-chunk for GEMM1 weight staging
#define NC 128     // output-column tile for GEMM2
#define XPAD 36    // padded row stride for transposed tiles

// ---- device-global scratch (no allocation allowed) ----
__device__ int g_counts[VV];
__device__ int g_bins[VV * BB];

__global__ void va_zero_counts() {
    if (threadIdx.x < VV) g_counts[threadIdx.x] = 0;
}

__global__ void va_bin(const int* __restrict__ vids) {
    int b = blockIdx.x * blockDim.x + threadIdx.x;
    if (b < BB) {
        int v = vids[b];
        int slot = atomicAdd(&g_counts[v], 1);
        g_bins[v * BB + slot] = b;
    }
}

__device__ __forceinline__ float gelu_tanh(float x) {
    // jax.nn.gelu default: approximate=True (tanh form)
    float x3 = x * x * x;
    float t = tanhf(0.7978845608028654f * (x + 0.044715f * x3));
    return 0.5f * x * (1.0f + t);
}

// Dynamic smem layout (floats):
//   sXt : [HH][XPAD]  transposed x tile   (768*36 = 27648)
//   sHt : [AA][XPAD]  transposed h tile   (128*36 = 4608)
//   sW  : [128][128]  weight staging      (16384)
#define SMEM_FLOATS (HH * XPAD + AA * XPAD + 128 * 128)

extern "C" __global__ void __launch_bounds__(256, 1)
va_main(const float* __restrict__ lh,
        const float* __restrict__ Wd, const float* __restrict__ bd,
        const float* __restrict__ Wu, const float* __restrict__ bu,
        const float* __restrict__ Wc, const float* __restrict__ bc,
        float* __restrict__ out) {
    extern __shared__ float smem[];
    float* sXt = smem;                       // [k][row], pad XPAD
    float* sHt = smem + HH * XPAD;           // [k][row], pad XPAD
    float* sW  = smem + HH * XPAD + AA * XPAD;

    __shared__ int sB[MTILE];

    const int v    = blockIdx.x;
    const int cnt  = g_counts[v];
    const int row0 = blockIdx.y * MTILE;
    if (row0 >= cnt) return;

    const int tid  = threadIdx.x;
    const int lane = tid & 31;   // cx: output-column group
    const int warp = tid >> 5;   // ry: output-row group

    if (tid < MTILE) {
        int gr = row0 + tid;
        sB[tid] = (gr < cnt) ? g_bins[v * BB + gr] : -1;
    }
    __syncthreads();

    // ---- gather 32 x-rows (t=0) into transposed smem ----
    for (int idx = tid; idx < MTILE * (HH / 4); idx += 256) {
        int r  = idx / (HH / 4);
        int k4 = idx % (HH / 4);
        int b  = sB[r];
        float4 val = make_float4(0.f, 0.f, 0.f, 0.f);
        if (b >= 0)
            val = *(const float4*)(lh + (size_t)b * TT * HH + k4 * 4);
        sXt[(k4 * 4 + 0) * XPAD + r] = val.x;
        sXt[(k4 * 4 + 1) * XPAD + r] = val.y;
        sXt[(k4 * 4 + 2) * XPAD + r] = val.z;
        sXt[(k4 * 4 + 3) * XPAD + r] = val.w;
    }
    __syncthreads();

    // ---- GEMM1: C[32][128] = X[32][768] @ Wd[v][768][128] ----
    const float* Wdv = Wd + (size_t)v * HH * AA;
    float acc[4][4];
    #pragma unroll
    for (int i = 0; i < 4; i++)
        #pragma unroll
        for (int j = 0; j < 4; j++) acc[i][j] = 0.f;

    for (int k0 = 0; k0 < HH; k0 += KC) {
        for (int idx = tid; idx < KC * AA / 4; idx += 256) {
            int kk = idx / (AA / 4);
            int a4 = idx % (AA / 4);
            *(float4*)(sW + kk * AA + a4 * 4) =
                *(const float4*)(Wdv + (size_t)(k0 + kk) * AA + a4 * 4);
        }
        __syncthreads();
        #pragma unroll 4
        for (int kk = 0; kk < KC; kk++) {
            float4 a4 = *(float4*)(sXt + (k0 + kk) * XPAD + 4 * warp);
            float4 b4 = *(float4*)(sW + kk * AA + 4 * lane);
            float av[4] = {a4.x, a4.y, a4.z, a4.w};
            float bv[4] = {b4.x, b4.y, b4.z, b4.w};
            #pragma unroll
            for (int i = 0; i < 4; i++)
                #pragma unroll
                for (int j = 0; j < 4; j++)
                    acc[i][j] = fmaf(av[i], bv[j], acc[i][j]);
        }
        __syncthreads();
    }

    // ---- bias + gelu -> sHt transposed ----
    const float* bdv = bd + v * AA;
    #pragma unroll
    for (int j = 0; j < 4; j++) {
        int col = 4 * lane + j;
        float bcol = bdv[col];
        #pragma unroll
        for (int i = 0; i < 4; i++) {
            float g = gelu_tanh(acc[i][j] + bcol);
            sHt[col * XPAD + (4 * warp + i)] = g;
        }
    }
    __syncthreads();

    // ---- GEMM2 (col tiles) + fused residual + classifier head ----
    const float* Wuv = Wu + (size_t)v * AA * HH;
    const float* buv = bu + v * HH;
    float outacc[4][2];
    #pragma unroll
    for (int i = 0; i < 4; i++) { outacc[i][0] = 0.f; outacc[i][1] = 0.f; }

    for (int c0 = 0; c0 < HH; c0 += NC) {
        for (int idx = tid; idx < AA * NC / 4; idx += 256) {
            int kk = idx / (NC / 4);
            int c4 = idx % (NC / 4);
            *(float4*)(sW + kk * NC + c4 * 4) =
                *(const float4*)(Wuv + (size_t)kk * HH + c0 + c4 * 4);
        }
        __syncthreads();

        float acc2[4][4];
        #pragma unroll
        for (int i = 0; i < 4; i++)
            #pragma unroll
            for (int j = 0; j < 4; j++) acc2[i][j] = 0.f;

        #pragma unroll 4
        for (int kk = 0; kk < AA; kk++) {
            float4 a4 = *(float4*)(sHt + kk * XPAD + 4 * warp);
            float4 b4 = *(float4*)(sW + kk * NC + 4 * lane);
            float av[4] = {a4.x, a4.y, a4.z, a4.w};
            float bv[4] = {b4.x, b4.y, b4.z, b4.w};
            #pragma unroll
            for (int i = 0; i < 4; i++)
                #pragma unroll
                for (int j = 0; j < 4; j++)
                    acc2[i][j] = fmaf(av[i], bv[j], acc2[i][j]);
        }

        // epilogue: adapted = x + (u + bu); out += adapted * Wc^T
        #pragma unroll
        for (int j = 0; j < 4; j++) {
            int col = c0 + 4 * lane + j;
            float bucol = buv[col];
            float wc0 = Wc[col];
            float wc1 = Wc[HH + col];
            #pragma unroll
            for (int i = 0; i < 4; i++) {
                float u  = acc2[i][j] + bucol;
                float ad = sXt[col * XPAD + (4 * warp + i)] + u;
                outacc[i][0] = fmaf(ad, wc0, outacc[i][0]);
                outacc[i][1] = fmaf(ad, wc1, outacc[i][1]);
            }
        }
        __syncthreads();
    }

    // ---- warp reduction across the 32 column-group lanes ----
    #pragma unroll
    for (int i = 0; i < 4; i++) {
        #pragma unroll
        for (int l = 0; l < 2; l++) {
            float s = outacc[i][l];
            #pragma unroll
            for (int off = 16; off; off >>= 1)
                s += __shfl_xor_sync(0xFFFFFFFFu, s, off);
            if (lane == 0) {
                int r = 4 * warp + i;
                int b = sB[r];
                if (b >= 0) out[b * LL + l] = s + bc[l];
            }
        }
    }
}

extern "C" void kernel_launch(void* const* d_in, const int* in_sizes, int n_in,
                              void* d_out, int out_size) {
    const float* lh   = (const float*)d_in[0];
    // d_in[1] = attention_mask (int64) — unused by the reference math
    const int*   vids = (const int*)d_in[2];
    const float* Wd   = (const float*)d_in[3];
    const float* bd   = (const float*)d_in[4];
    const float* Wu   = (const float*)d_in[5];
    const float* bu   = (const float*)d_in[6];
    const float* Wc   = (const float*)d_in[7];
    const float* bc   = (const float*)d_in[8];
    float* out = (float*)d_out;

    size_t smem_bytes = SMEM_FLOATS * sizeof(float);
    cudaFuncSetAttribute(va_main, cudaFuncAttributeMaxDynamicSharedMemorySize,
                         (int)smem_bytes);

    va_zero_counts<<<1, 32>>>();
    va_bin<<<BB / 256, 256>>>(vids);
    dim3 grid(VV, BB / MTILE);
    va_main<<<grid, 256, smem_bytes>>>(lh, Wd, bd, Wu, bu, Wc, bc, out);
}

// round 2
// speedup vs baseline: 1.2034x; 1.2034x over previous
#include <cuda_runtime.h>

#define BB 4096
#define TT 16
#define HH 768
#define AA 128
#define VV 16
#define LL 2
#define MTILE 32
#define KC 64
#define NC 128
#define XPAD 36
#define NTHREADS 256
#define MAXTILES 160

// ---- device-global scratch ----
__device__ int g_counts[VV];
__device__ int g_bins[VV * BB];
__device__ int g_ntiles;
__device__ int g_tiles[MAXTILES];

__global__ void va_zero_counts() {
    if (threadIdx.x < VV) g_counts[threadIdx.x] = 0;
}

__global__ void va_bin(const int* __restrict__ vids) {
    int b = blockIdx.x * blockDim.x + threadIdx.x;
    if (b < BB) {
        int v = vids[b];
        int slot = atomicAdd(&g_counts[v], 1);
        g_bins[v * BB + slot] = b;
    }
}

__global__ void va_build_tiles() {
    if (threadIdx.x == 0) {
        int t = 0;
        for (int v = 0; v < VV; v++) {
            int c = g_counts[v];
            for (int r0 = 0; r0 < c; r0 += MTILE)
                g_tiles[t++] = (v << 16) | (r0 / MTILE);
        }
        g_ntiles = t;
    }
}

// ---- f32x2 packed-FMA helpers (sm_103a FFMA2 path) ----
typedef unsigned long long u64t;

__device__ __forceinline__ u64t dup2(float x) {
    u64t r;
    asm("mov.b64 %0, {%1, %1};" : "=l"(r) : "f"(x));
    return r;
}
__device__ __forceinline__ u64t fma2(u64t a, u64t b, u64t c) {
    u64t d;
    asm("fma.rn.f32x2 %0, %1, %2, %3;" : "=l"(d) : "l"(a), "l"(b), "l"(c));
    return d;
}
__device__ __forceinline__ float2 upk(u64t d) {
    float2 f;
    asm("mov.b64 {%0, %1}, %2;" : "=f"(f.x), "=f"(f.y) : "l"(d));
    return f;
}

__device__ __forceinline__ float gelu_tanh(float x) {
    float x3 = x * x * x;
    float t = tanhf(0.7978845608028654f * (x + 0.044715f * x3));
    return 0.5f * x * (1.0f + t);
}

// smem: sXt[HH][XPAD] + sHt[AA][XPAD] + sW[128*128]
#define SMEM_FLOATS (HH * XPAD + AA * XPAD + 128 * 128)

extern "C" __global__ void __launch_bounds__(NTHREADS, 1)
va_main(const float* __restrict__ lh,
        const float* __restrict__ Wd, const float* __restrict__ bd,
        const float* __restrict__ Wu, const float* __restrict__ bu,
        const float* __restrict__ Wc, const float* __restrict__ bc,
        float* __restrict__ out) {
    extern __shared__ float smem[];
    float* sXt = smem;
    float* sHt = smem + HH * XPAD;
    float* sW  = smem + HH * XPAD + AA * XPAD;
    __shared__ int sB[MTILE];

    const int tid  = threadIdx.x;
    const int lane = tid & 31;
    const int warp = tid >> 5;
    const int r8   = lane & 7;    // row group: rows 4*r8 .. 4*r8+3
    const int c4   = lane >> 3;   // col group within warp
    const int colbase = 16 * warp + 4 * c4;   // thread's 4 output cols (mod tile)

    const int ntiles = g_ntiles;

    for (int t = blockIdx.x; t < ntiles; t += gridDim.x) {
        const int info = g_tiles[t];
        const int v    = info >> 16;
        const int row0 = (info & 0xFFFF) * MTILE;
        const int cnt  = g_counts[v];

        if (tid < MTILE) {
            int gr = row0 + tid;
            sB[tid] = (gr < cnt) ? g_bins[v * BB + gr] : -1;
        }
        __syncthreads();

        // ---- gather 32 x rows (t=0) transposed into sXt ----
        for (int idx = tid; idx < MTILE * (HH / 4); idx += NTHREADS) {
            int r  = idx / (HH / 4);
            int k4 = idx % (HH / 4);
            int b  = sB[r];
            float4 val = make_float4(0.f, 0.f, 0.f, 0.f);
            if (b >= 0)
                val = *(const float4*)(lh + (size_t)b * TT * HH + k4 * 4);
            sXt[(k4 * 4 + 0) * XPAD + r] = val.x;
            sXt[(k4 * 4 + 1) * XPAD + r] = val.y;
            sXt[(k4 * 4 + 2) * XPAD + r] = val.z;
            sXt[(k4 * 4 + 3) * XPAD + r] = val.w;
        }

        // ================= GEMM1: H[32][128] = X[32][768] @ Wd[v] =================
        const float* Wdv = Wd + (size_t)v * HH * AA;
        float4 pf[8];
        #pragma unroll
        for (int q = 0; q < 8; q++)
            pf[q] = *(const float4*)(Wdv + (size_t)(q * NTHREADS + tid) * 4);

        u64t acc1[4][2];
        #pragma unroll
        for (int i = 0; i < 4; i++) { acc1[i][0] = 0ull; acc1[i][1] = 0ull; }

        __syncthreads();   // sXt gather complete

        for (int k0 = 0; k0 < HH; k0 += KC) {
            #pragma unroll
            for (int q = 0; q < 8; q++)
                *(float4*)(sW + (q * NTHREADS + tid) * 4) = pf[q];
            __syncthreads();
            if (k0 + KC < HH) {
                const float* src = Wdv + (size_t)(k0 + KC) * AA;
                #pragma unroll
                for (int q = 0; q < 8; q++)
                    pf[q] = *(const float4*)(src + (size_t)(q * NTHREADS + tid) * 4);
            }
            #pragma unroll 4
            for (int kk = 0; kk < KC; kk++) {
                float4 a4 = *(const float4*)(sXt + (k0 + kk) * XPAD + 4 * r8);
                double2 bp = *(const double2*)(sW + kk * AA + colbase);
                u64t b01 = __double_as_longlong(bp.x);
                u64t b23 = __double_as_longlong(bp.y);
                u64t a0 = dup2(a4.x), a1 = dup2(a4.y), a2 = dup2(a4.z), a3 = dup2(a4.w);
                acc1[0][0] = fma2(a0, b01, acc1[0][0]); acc1[0][1] = fma2(a0, b23, acc1[0][1]);
                acc1[1][0] = fma2(a1, b01, acc1[1][0]); acc1[1][1] = fma2(a1, b23, acc1[1][1]);
                acc1[2][0] = fma2(a2, b01, acc1[2][0]); acc1[2][1] = fma2(a2, b23, acc1[2][1]);
                acc1[3][0] = fma2(a3, b01, acc1[3][0]); acc1[3][1] = fma2(a3, b23, acc1[3][1]);
            }
            __syncthreads();
        }

        // ---- GEMM2 stage-0 prefetch (overlaps with GEMM1 epilogue) ----
        const float* Wuv = Wu + (size_t)v * AA * HH;
        float4 pf2[16];
        #pragma unroll
        for (int q = 0; q < 16; q++) {
            int idx4 = q * NTHREADS + tid;
            int a    = idx4 >> 5;           // 32 float4 per 128-col row
            int cc4  = idx4 & 31;
            pf2[q] = *(const float4*)(Wuv + (size_t)a * HH + 0 + cc4 * 4);
        }

        // ---- bias + gelu -> sHt transposed ----
        {
            const float* bdv = bd + v * AA;
            float g[4][4];   // [j][i]
            #pragma unroll
            for (int i = 0; i < 4; i++) {
                float2 f01 = upk(acc1[i][0]);
                float2 f23 = upk(acc1[i][1]);
                float u0 = f01.x, u1 = f01.y, u2 = f23.x, u3 = f23.y;
                g[0][i] = gelu_tanh(u0 + bdv[colbase + 0]);
                g[1][i] = gelu_tanh(u1 + bdv[colbase + 1]);
                g[2][i] = gelu_tanh(u2 + bdv[colbase + 2]);
                g[3][i] = gelu_tanh(u3 + bdv[colbase + 3]);
            }
            #pragma unroll
            for (int j = 0; j < 4; j++)
                *(float4*)(sHt + (colbase + j) * XPAD + 4 * r8) =
                    make_float4(g[j][0], g[j][1], g[j][2], g[j][3]);
        }
        __syncthreads();

        // ======= GEMM2 (col tiles of 128) + fused residual + classifier =======
        const float* buv = bu + v * HH;
        float outacc[4][2];
        #pragma unroll
        for (int i = 0; i < 4; i++) { outacc[i][0] = 0.f; outacc[i][1] = 0.f; }

        for (int c0 = 0; c0 < HH; c0 += NC) {
            #pragma unroll
            for (int q = 0; q < 16; q++) {
                int idx4 = q * NTHREADS + tid;
                int a    = idx4 >> 5;
                int cc4  = idx4 & 31;
                *(float4*)(sW + a * NC + cc4 * 4) = pf2[q];
            }
            __syncthreads();
            if (c0 + NC < HH) {
                #pragma unroll
                for (int q = 0; q < 16; q++) {
                    int idx4 = q * NTHREADS + tid;
                    int a    = idx4 >> 5;
                    int cc4  = idx4 & 31;
                    pf2[q] = *(const float4*)(Wuv + (size_t)a * HH + (c0 + NC) + cc4 * 4);
                }
            }

            u64t acc2[4][2];
            #pragma unroll
            for (int i = 0; i < 4; i++) { acc2[i][0] = 0ull; acc2[i][1] = 0ull; }

            #pragma unroll 4
            for (int kk = 0; kk < AA; kk++) {
                float4 a4 = *(const float4*)(sHt + kk * XPAD + 4 * r8);
                double2 bp = *(const double2*)(sW + kk * NC + colbase);
                u64t b01 = __double_as_longlong(bp.x);
                u64t b23 = __double_as_longlong(bp.y);
                u64t a0 = dup2(a4.x), a1 = dup2(a4.y), a2 = dup2(a4.z), a3 = dup2(a4.w);
                acc2[0][0] = fma2(a0, b01, acc2[0][0]); acc2[0][1] = fma2(a0, b23, acc2[0][1]);
                acc2[1][0] = fma2(a1, b01, acc2[1][0]); acc2[1][1] = fma2(a1, b23, acc2[1][1]);
                acc2[2][0] = fma2(a2, b01, acc2[2][0]); acc2[2][1] = fma2(a2, b23, acc2[2][1]);
                acc2[3][0] = fma2(a3, b01, acc2[3][0]); acc2[3][1] = fma2(a3, b23, acc2[3][1]);
            }

            // epilogue: adapted = x + (u + bu); out += adapted * Wc^T
            float uu[4][4];   // [i][j]
            #pragma unroll
            for (int i = 0; i < 4; i++) {
                float2 f01 = upk(acc2[i][0]);
                float2 f23 = upk(acc2[i][1]);
                uu[i][0] = f01.x; uu[i][1] = f01.y; uu[i][2] = f23.x; uu[i][3] = f23.y;
            }
            #pragma unroll
            for (int j = 0; j < 4; j++) {
                int col = c0 + colbase + j;
                float bucol = buv[col];
                float wc0 = Wc[col];
                float wc1 = Wc[HH + col];
                float4 xr = *(const float4*)(sXt + col * XPAD + 4 * r8);
                float xv[4] = {xr.x, xr.y, xr.z, xr.w};
                #pragma unroll
                for (int i = 0; i < 4; i++) {
                    float ad = xv[i] + uu[i][j] + bucol;
                    outacc[i][0] = fmaf(ad, wc0, outacc[i][0]);
                    outacc[i][1] = fmaf(ad, wc1, outacc[i][1]);
                }
            }
            __syncthreads();
        }

        // ---- reduce over c4 (lanes xor 8,16), then over warps via smem ----
        #pragma unroll
        for (int i = 0; i < 4; i++)
            #pragma unroll
            for (int l = 0; l < 2; l++) {
                float s = outacc[i][l];
                s += __shfl_xor_sync(0xFFFFFFFFu, s, 8);
                s += __shfl_xor_sync(0xFFFFFFFFu, s, 16);
                outacc[i][l] = s;
            }
        float* sRed = sW;   // free after last sync
        if (c4 == 0) {
            #pragma unroll
            for (int i = 0; i < 4; i++) {
                int row = 4 * r8 + i;
                sRed[(warp * MTILE + row) * 2 + 0] = outacc[i][0];
                sRed[(warp * MTILE + row) * 2 + 1] = outacc[i][1];
            }
        }
        __syncthreads();
        if (tid < MTILE * LL) {
            int row = tid >> 1;
            int l   = tid & 1;
            float s = bc[l];
            #pragma unroll
            for (int w = 0; w < 8; w++)
                s += sRed[(w * MTILE + row) * 2 + l];
            int b = sB[row];
            if (b >= 0) out[b * LL + l] = s;
        }
        __syncthreads();
    }
}

extern "C" void kernel_launch(void* const* d_in, const int* in_sizes, int n_in,
                              void* d_out, int out_size) {
    const float* lh   = (const float*)d_in[0];
    const int*   vids = (const int*)d_in[2];
    const float* Wd   = (const float*)d_in[3];
    const float* bd   = (const float*)d_in[4];
    const float* Wu   = (const float*)d_in[5];
    const float* bu   = (const float*)d_in[6];
    const float* Wc   = (const float*)d_in[7];
    const float* bc   = (const float*)d_in[8];
    float* out = (float*)d_out;

    size_t smem_bytes = SMEM_FLOATS * sizeof(float);
    cudaFuncSetAttribute(va_main, cudaFuncAttributeMaxDynamicSharedMemorySize,
                         (int)smem_bytes);

    va_zero_counts<<<1, 32>>>();
    va_bin<<<BB / 256, 256>>>(vids);
    va_build_tiles<<<1, 32>>>();
    va_main<<<148, NTHREADS, smem_bytes>>>(lh, Wd, bd, Wu, bu, Wc, bc, out);
}